// round 4
// baseline (speedup 1.0000x reference)
#include <cuda_runtime.h>

#define NPTS    16384
#define NB      1024
#define XMIN    (-5.0f)
#define XW      (10.0f / (float)NB)      // bin width
#define INVW    ((float)NB / 10.0f)
#define TPB     128                       // search block threads == queries/block
#define NBLK    (NPTS / TPB)              // 128 search blocks per pass
#define EXPBINS 4                         // bins added per side per expansion

typedef unsigned int u32;

// set 0 = predict, set 1 = target
__device__ u32    g_cnt[2][NB];
__device__ u32    g_cur[2][NB];
__device__ int    g_off[2][NB + 1];
__device__ float4 g_pts[2][NPTS];         // binned points (x,y,z, 0.5*|p|^2)
__device__ int    g_idx[2][NPTS];         // original index of binned point
__device__ float  g_d2[2][NPTS];          // per-query min squared distance (by orig idx)

__device__ __forceinline__ int bin_of(float x) {
    int b = (int)((x - XMIN) * INVW);
    return min(max(b, 0), NB - 1);
}

// ---------- K0: zero counters ----------
__global__ void k_zero() {
    int i = blockIdx.x * blockDim.x + threadIdx.x;
    if (i < 2 * NB) {
        ((u32*)g_cnt)[i] = 0;
        ((u32*)g_cur)[i] = 0;
    }
}

// ---------- K1: histogram ----------
__global__ void k_count(const float* __restrict__ pr, const float* __restrict__ tg) {
    int i = blockIdx.x * blockDim.x + threadIdx.x;
    if (i >= 2 * NPTS) return;
    int s = (i >= NPTS);
    int j = i - s * NPTS;
    const float* src = s ? tg : pr;
    float x = src[3 * j];
    atomicAdd(&g_cnt[s][bin_of(x)], 1u);
}

// ---------- K2: prefix sums (one block, NB threads) ----------
__global__ void __launch_bounds__(NB) k_scan() {
    __shared__ int sh[NB];
    int tid = threadIdx.x;
#pragma unroll
    for (int s = 0; s < 2; s++) {
        sh[tid] = (int)g_cnt[s][tid];
        __syncthreads();
        for (int d = 1; d < NB; d <<= 1) {
            int v = sh[tid];
            if (tid >= d) v += sh[tid - d];
            __syncthreads();
            sh[tid] = v;
            __syncthreads();
        }
        g_off[s][tid + 1] = sh[tid];
        if (tid == 0) g_off[s][0] = 0;
        __syncthreads();
    }
}

// ---------- K3: scatter into binned order ----------
__global__ void k_scatter(const float* __restrict__ pr, const float* __restrict__ tg) {
    int i = blockIdx.x * blockDim.x + threadIdx.x;
    if (i >= 2 * NPTS) return;
    int s = (i >= NPTS);
    int j = i - s * NPTS;
    const float* src = s ? tg : pr;
    float x = src[3 * j], y = src[3 * j + 1], z = src[3 * j + 2];
    int b = bin_of(x);
    int pos = g_off[s][b] + (int)atomicAdd(&g_cur[s][b], 1u);
    g_pts[s][pos] = make_float4(x, y, z, 0.5f * (x * x + y * y + z * z));
    g_idx[s][pos] = j;
}

// ---------- eval a ref range [beg,end) block-cooperatively ----------
__device__ __forceinline__ void eval_range(const float4* __restrict__ refs,
                                           int beg, int end,
                                           float nqx, float nqy, float nqz,
                                           float& m0, float& m1,
                                           float4* s_chunk, int tid) {
    for (int base = beg; base < end; base += TPB) {
        int n = min(TPB, end - base);
        __syncthreads();
        if (tid < n) s_chunk[tid] = refs[base + tid];
        __syncthreads();
        int j = 0;
        for (; j + 2 <= n; j += 2) {
            float4 t0 = s_chunk[j];
            float4 t1 = s_chunk[j + 1];
            float e0 = __fmaf_rn(nqx, t0.x, t0.w);
            e0 = __fmaf_rn(nqy, t0.y, e0);
            e0 = __fmaf_rn(nqz, t0.z, e0);
            float e1 = __fmaf_rn(nqx, t1.x, t1.w);
            e1 = __fmaf_rn(nqy, t1.y, e1);
            e1 = __fmaf_rn(nqz, t1.z, e1);
            m0 = fminf(m0, e0);
            m1 = fminf(m1, e1);
        }
        if (j < n) {
            float4 t0 = s_chunk[j];
            float e0 = __fmaf_rn(nqx, t0.x, t0.w);
            e0 = __fmaf_rn(nqy, t0.y, e0);
            e0 = __fmaf_rn(nqz, t0.z, e0);
            m0 = fminf(m0, e0);
        }
    }
}

// ---------- K4: pruned exact NN search ----------
// blockIdx.y = pass (0: queries=predict vs refs=target; 1: reverse)
__global__ void __launch_bounds__(TPB)
k_search() {
    __shared__ float4 s_chunk[TPB];
    __shared__ int s_lo, s_hi;

    const int pass = blockIdx.y;
    const int qset = pass, rset = 1 - pass;
    const int tid = threadIdx.x;
    const int qpos = blockIdx.x * TPB + tid;

    const float4 q = g_pts[qset][qpos];
    const int myidx = g_idx[qset][qpos];
    const float nqx = -q.x, nqy = -q.y, nqz = -q.z;

    int qb = bin_of(q.x);
    if (tid == 0) s_lo = qb;
    if (tid == TPB - 1) s_hi = qb;
    __syncthreads();

    int l = max(s_lo - 2, 0);
    int r = min(s_hi + 2, NB - 1);

    const float4* __restrict__ refs = g_pts[rset];
    const int* __restrict__ off = g_off[rset];

    const float INF = __int_as_float(0x7f800000);
    float m0 = INF, m1 = INF;

    eval_range(refs, off[l], off[r + 1], nqx, nqy, nqz, m0, m1, s_chunk, tid);

    while (true) {
        float m = fminf(m0, m1);
        float myd2 = fmaxf(2.0f * (m + q.w), 0.0f);
        float bndL = XMIN + (float)l * XW;
        float bndR = XMIN + (float)(r + 1) * XW;
        float dl = q.x - bndL;            // >= 0 whenever l > 0
        float dr = bndR - q.x;            // >= 0 whenever r < NB-1
        int needL = (l > 0) && (dl * dl < myd2);
        int needR = (r < NB - 1) && (dr * dr < myd2);
        int anyL = __syncthreads_or(needL);
        int anyR = __syncthreads_or(needR);
        if (!anyL && !anyR) break;

        int nl = anyL ? max(l - EXPBINS, 0) : l;
        int nr = anyR ? min(r + EXPBINS, NB - 1) : r;
        if (anyL) eval_range(refs, off[nl], off[l], nqx, nqy, nqz, m0, m1, s_chunk, tid);
        if (anyR) eval_range(refs, off[r + 1], off[nr + 1], nqx, nqy, nqz, m0, m1, s_chunk, tid);
        l = nl; r = nr;
    }

    float m = fminf(m0, m1);
    g_d2[pass][myidx] = fmaxf(2.0f * (m + q.w), 0.0f);
}

// ---------- K5: deterministic fixed-order reduction ----------
__global__ void __launch_bounds__(1024)
k_reduce(float* __restrict__ out) {
    __shared__ float sh[1024];
    const float* d2 = (const float*)g_d2;   // 2*NPTS floats
    float s = 0.0f;
    for (int i = threadIdx.x; i < 2 * NPTS; i += 1024)
        s += d2[i];
    sh[threadIdx.x] = s;
    __syncthreads();
#pragma unroll
    for (int offd = 512; offd > 0; offd >>= 1) {
        if (threadIdx.x < offd) sh[threadIdx.x] += sh[threadIdx.x + offd];
        __syncthreads();
    }
    if (threadIdx.x == 0)
        out[0] = sh[0] * (1.0f / (float)NPTS);
}

extern "C" void kernel_launch(void* const* d_in, const int* in_sizes, int n_in,
                              void* d_out, int out_size) {
    const float* pr = (const float*)d_in[0];   // predict [1,16384,3]
    const float* tg = (const float*)d_in[1];   // target  [1,16384,3]
    float* out = (float*)d_out;

    k_zero<<<(2 * NB + 255) / 256, 256>>>();
    k_count<<<(2 * NPTS + 255) / 256, 256>>>(pr, tg);
    k_scan<<<1, NB>>>();
    k_scatter<<<(2 * NPTS + 255) / 256, 256>>>(pr, tg);

    dim3 grid(NBLK, 2);
    k_search<<<grid, TPB>>>();

    k_reduce<<<1, 1024>>>(out);
}